// round 16
// baseline (speedup 1.0000x reference)
#include <cuda_runtime.h>
#include <cuda_bf16.h>
#include <cuda_fp16.h>
#include <cstdint>

#define D 128
#define MAX_N 100000
#define MAX_E 1600000

// ---------------- scratch (static device globals; no allocation) ----------------
// NOTE: g_cnt / g_blk_flag / g_blk_aggr are zero at module load and re-zeroed by
// agg_kernel (the last graph node) for the next invocation -> no prep on the
// critical path. Deterministic: every call does identical work on zeroed state.
__device__ __align__(16) __half g_h16[(size_t)MAX_N * D];   // x @ W, fp16
__device__ __align__(16) int   g_cnt[MAX_N + 4];            // zero-init + agg epilogue reset
__device__ int   g_rowstart[MAX_N + 1];
__device__ __align__(16) unsigned short g_slot16[MAX_E];    // per-edge slot within its row (u16)
__device__ __align__(16) uint2 g_edge[MAX_E];               // packed {col, val}
__device__ __align__(16) __nv_bfloat16 g_wt_hi[D * D];      // W^T split, [n][k]
__device__ __align__(16) __nv_bfloat16 g_wt_lo[D * D];
__device__ int   g_blk_aggr[128];                           // zero-init + agg epilogue reset
__device__ int   g_blk_flag[128];                           // zero-init + agg epilogue reset

// ---------------- side stream + events for graph-captured fork/join ----------------
static cudaStream_t g_s1 = nullptr;
static cudaEvent_t  g_ev_fork = nullptr, g_ev_join = nullptr;
namespace {
struct StreamInit {
    StreamInit() {
        if (cudaStreamCreateWithFlags(&g_s1, cudaStreamNonBlocking) != cudaSuccess) g_s1 = nullptr;
        if (cudaEventCreateWithFlags(&g_ev_fork, cudaEventDisableTiming) != cudaSuccess) g_ev_fork = nullptr;
        if (cudaEventCreateWithFlags(&g_ev_join, cudaEventDisableTiming) != cudaSuccess) g_ev_join = nullptr;
    }
};
static StreamInit s_init;
}

// =============== W split only (GEMM branch, off the critical path) ===============
__global__ void wsplit_kernel(const float* __restrict__ w)
{
    int i = blockIdx.x * blockDim.x + threadIdx.x;   // 0..16383
    if (i < D * D) {
        int k = i >> 7, nn = i & 127;
        float v = w[i];                               // w[k*128+n]
        __nv_bfloat16 hi = __float2bfloat16_rn(v);
        float lo = v - __bfloat162float(hi);
        g_wt_hi[nn * D + k] = hi;
        g_wt_lo[nn * D + k] = __float2bfloat16_rn(lo);
    }
}

// ---------------- CSR build ----------------
// hist also assigns each edge its slot within its row (atomic return value, u16)
__global__ void hist_kernel(const int* __restrict__ rows, int e)
{
    int i0 = (blockIdx.x * blockDim.x + threadIdx.x) * 4;
    if (i0 + 3 < e) {
        int4 r = *(const int4*)(rows + i0);
        ushort4 s;
        s.x = (unsigned short)atomicAdd(&g_cnt[r.x], 1);
        s.y = (unsigned short)atomicAdd(&g_cnt[r.y], 1);
        s.z = (unsigned short)atomicAdd(&g_cnt[r.z], 1);
        s.w = (unsigned short)atomicAdd(&g_cnt[r.w], 1);
        *(ushort4*)(g_slot16 + i0) = s;               // coalesced 8B store
    } else {
        for (int i = i0; i < e; i++)
            g_slot16[i] = (unsigned short)atomicAdd(&g_cnt[rows[i]], 1);
    }
}

// single-pass scan, 4 elems/thread, shuffle-based; decoupled lookback (25 blocks, 1 wave)
__global__ void scan_kernel(int n)
{
    __shared__ int warpsum[32];
    __shared__ int pref;
    const int b = blockIdx.x;
    const int tid = threadIdx.x;
    const int lane = tid & 31, wid = tid >> 5;
    const int base = b * 4096 + tid * 4;

    int4 v = make_int4(0, 0, 0, 0);
    if (base + 3 < n) {
        v = *(const int4*)(g_cnt + base);
    } else {
        if (base + 0 < n) v.x = g_cnt[base + 0];
        if (base + 1 < n) v.y = g_cnt[base + 1];
        if (base + 2 < n) v.z = g_cnt[base + 2];
        if (base + 3 < n) v.w = g_cnt[base + 3];
    }
    int s1 = v.x + v.y, s2 = s1 + v.z, s3 = s2 + v.w;
    int tsum = s3;

    int sc = tsum;
    #pragma unroll
    for (int o = 1; o < 32; o <<= 1) {
        int t = __shfl_up_sync(0xFFFFFFFFu, sc, o);
        if (lane >= o) sc += t;
    }
    if (lane == 31) warpsum[wid] = sc;
    if (tid == 0) pref = 0;
    __syncthreads();
    if (wid == 0) {
        int ws = warpsum[lane];
        #pragma unroll
        for (int o = 1; o < 32; o <<= 1) {
            int t = __shfl_up_sync(0xFFFFFFFFu, ws, o);
            if (lane >= o) ws += t;
        }
        warpsum[lane] = ws;
    }
    __syncthreads();

    if (tid == 0) {
        g_blk_aggr[b] = warpsum[31];
        __threadfence();
        atomicExch(&g_blk_flag[b], 1);
    }
    if (tid < b) {
        while (atomicAdd(&g_blk_flag[tid], 0) == 0) { }
        atomicAdd(&pref, g_blk_aggr[tid]);
    }
    __syncthreads();

    const int wpref = (wid > 0) ? warpsum[wid - 1] : 0;
    const int off = pref + wpref + (sc - tsum);

    if (base + 0 < n) g_rowstart[base + 1] = off + v.x;
    if (base + 1 < n) g_rowstart[base + 2] = off + s1;
    if (base + 2 < n) g_rowstart[base + 3] = off + s2;
    if (base + 3 < n) g_rowstart[base + 4] = off + s3;
    if (b == 0 && tid == 0) g_rowstart[0] = 0;
}

// atomic-free fill: position = rowstart[row] + precomputed slot
__global__ void fill_kernel(const int* __restrict__ rows, const int* __restrict__ cols,
                            const float* __restrict__ vals, int e)
{
    int i0 = (blockIdx.x * blockDim.x + threadIdx.x) * 4;
    if (i0 + 3 < e) {
        int4    r = *(const int4*)(rows + i0);
        int4    c = *(const int4*)(cols + i0);
        float4  v = *(const float4*)(vals + i0);
        ushort4 s = *(const ushort4*)(g_slot16 + i0);
        int p0 = g_rowstart[r.x] + s.x;
        int p1 = g_rowstart[r.y] + s.y;
        int p2 = g_rowstart[r.z] + s.z;
        int p3 = g_rowstart[r.w] + s.w;
        g_edge[p0] = make_uint2((unsigned)c.x, __float_as_uint(v.x));
        g_edge[p1] = make_uint2((unsigned)c.y, __float_as_uint(v.y));
        g_edge[p2] = make_uint2((unsigned)c.z, __float_as_uint(v.z));
        g_edge[p3] = make_uint2((unsigned)c.w, __float_as_uint(v.w));
    } else {
        for (int i = i0; i < e; i++) {
            int p = g_rowstart[rows[i]] + (int)g_slot16[i];
            g_edge[p] = make_uint2((unsigned)cols[i], __float_as_uint(vals[i]));
        }
    }
}

// =============== GEMM: h = x @ W via mma.sync bf16, 3-product split ===============
#define AS 136
#define SM_AHI 0
#define SM_ALO (128 * AS * 2)
#define SM_BHI (2 * 128 * AS * 2)
#define SM_BLO (3 * 128 * AS * 2)
#define SM_TOT (4 * 128 * AS * 2)

__device__ __forceinline__ void mma_bf16(float* c, const uint32_t* a, uint32_t b0, uint32_t b1)
{
    asm volatile(
        "mma.sync.aligned.m16n8k16.row.col.f32.bf16.bf16.f32 "
        "{%0,%1,%2,%3}, {%4,%5,%6,%7}, {%8,%9}, {%0,%1,%2,%3};"
        : "+f"(c[0]), "+f"(c[1]), "+f"(c[2]), "+f"(c[3])
        : "r"(a[0]), "r"(a[1]), "r"(a[2]), "r"(a[3]), "r"(b0), "r"(b1));
}

__global__ void __launch_bounds__(256, 1)
gemm_tc_kernel(const float* __restrict__ x, int n)
{
    extern __shared__ char smem[];
    __nv_bfloat16* sAhi = (__nv_bfloat16*)(smem + SM_AHI);
    __nv_bfloat16* sAlo = (__nv_bfloat16*)(smem + SM_ALO);
    __nv_bfloat16* sBhi = (__nv_bfloat16*)(smem + SM_BHI);
    __nv_bfloat16* sBlo = (__nv_bfloat16*)(smem + SM_BLO);

    const int tid = threadIdx.x;
    const int m0  = blockIdx.x * 128;

    #pragma unroll
    for (int t = 0; t < 8; t++) {
        int i = tid + 256 * t;
        int row = i >> 4, kc = (i & 15) * 8;
        uint4 vh = *(const uint4*)(g_wt_hi + row * D + kc);
        uint4 vl = *(const uint4*)(g_wt_lo + row * D + kc);
        *(uint4*)(sBhi + row * AS + kc) = vh;
        *(uint4*)(sBlo + row * AS + kc) = vl;
    }
    #pragma unroll
    for (int t = 0; t < 16; t++) {
        int i = tid + 256 * t;
        int row = i >> 5, c4 = (i & 31) * 4;
        int gm = m0 + row;
        float4 v = (gm < n) ? *(const float4*)(x + (size_t)gm * D + c4)
                            : make_float4(0.f, 0.f, 0.f, 0.f);
        __nv_bfloat16 h0 = __float2bfloat16_rn(v.x), h1 = __float2bfloat16_rn(v.y);
        __nv_bfloat16 h2 = __float2bfloat16_rn(v.z), h3 = __float2bfloat16_rn(v.w);
        __nv_bfloat16 l0 = __float2bfloat16_rn(v.x - __bfloat162float(h0));
        __nv_bfloat16 l1 = __float2bfloat16_rn(v.y - __bfloat162float(h1));
        __nv_bfloat16 l2 = __float2bfloat16_rn(v.z - __bfloat162float(h2));
        __nv_bfloat16 l3 = __float2bfloat16_rn(v.w - __bfloat162float(h3));
        uint32_t hp0 = ((uint32_t)__bfloat16_as_ushort(h1) << 16) | __bfloat16_as_ushort(h0);
        uint32_t hp1 = ((uint32_t)__bfloat16_as_ushort(h3) << 16) | __bfloat16_as_ushort(h2);
        uint32_t lp0 = ((uint32_t)__bfloat16_as_ushort(l1) << 16) | __bfloat16_as_ushort(l0);
        uint32_t lp1 = ((uint32_t)__bfloat16_as_ushort(l3) << 16) | __bfloat16_as_ushort(l2);
        uint2 hq; hq.x = hp0; hq.y = hp1;
        uint2 lq; lq.x = lp0; lq.y = lp1;
        *(uint2*)(sAhi + row * AS + c4) = hq;
        *(uint2*)(sAlo + row * AS + c4) = lq;
    }
    __syncthreads();

    const int wid  = tid >> 5;
    const int lane = tid & 31;
    const int g = lane >> 2, q = lane & 3;
    const int m_base = (wid & 3) * 32;
    const int n_base = (wid >> 2) * 64;

    float acc[2][8][4];
    #pragma unroll
    for (int mi = 0; mi < 2; mi++)
        #pragma unroll
        for (int ni = 0; ni < 8; ni++)
            #pragma unroll
            for (int r = 0; r < 4; r++) acc[mi][ni][r] = 0.f;

    #pragma unroll
    for (int prod = 0; prod < 3; prod++) {
        const __nv_bfloat16* A = (prod == 2) ? sAlo : sAhi;
        const __nv_bfloat16* B = (prod == 1) ? sBlo : sBhi;
        #pragma unroll
        for (int ks = 0; ks < 8; ks++) {
            const int k0 = ks * 16;
            uint32_t a[2][4];
            #pragma unroll
            for (int mi = 0; mi < 2; mi++) {
                const int r0 = m_base + mi * 16;
                a[mi][0] = *(const uint32_t*)(A + (r0 + g)     * AS + k0     + q * 2);
                a[mi][1] = *(const uint32_t*)(A + (r0 + g + 8) * AS + k0     + q * 2);
                a[mi][2] = *(const uint32_t*)(A + (r0 + g)     * AS + k0 + 8 + q * 2);
                a[mi][3] = *(const uint32_t*)(A + (r0 + g + 8) * AS + k0 + 8 + q * 2);
            }
            #pragma unroll
            for (int ni = 0; ni < 8; ni++) {
                const int nr = n_base + ni * 8 + g;
                uint32_t b0 = *(const uint32_t*)(B + nr * AS + k0     + q * 2);
                uint32_t b1 = *(const uint32_t*)(B + nr * AS + k0 + 8 + q * 2);
                mma_bf16(acc[0][ni], a[0], b0, b1);
                mma_bf16(acc[1][ni], a[1], b0, b1);
            }
        }
    }

    #pragma unroll
    for (int mi = 0; mi < 2; mi++) {
        const int r0 = m0 + m_base + mi * 16;
        #pragma unroll
        for (int ni = 0; ni < 8; ni++) {
            const int col = n_base + ni * 8 + q * 2;
            int ra = r0 + g, rb = r0 + g + 8;
            if (ra < n)
                *(__half2*)(g_h16 + (size_t)ra * D + col) =
                    __floats2half2_rn(acc[mi][ni][0], acc[mi][ni][1]);
            if (rb < n)
                *(__half2*)(g_h16 + (size_t)rb * D + col) =
                    __floats2half2_rn(acc[mi][ni][2], acc[mi][ni][3]);
        }
    }
}

// ---------------- aggregation: one warp per row + state reset for next invocation ----------------
__global__ void agg_kernel(float* __restrict__ out, int n)
{
    const int gid  = blockIdx.x * blockDim.x + threadIdx.x;
    // epilogue-style state recycle: reset cnt/flags for the NEXT graph replay
    // (zero at module load covers the first call)
    if (gid <= n) g_cnt[gid] = 0;
    if (gid < 128) { g_blk_flag[gid] = 0; g_blk_aggr[gid] = 0; }

    int gw   = gid >> 5;
    int lane = threadIdx.x & 31;
    if (gw >= n) return;

    int s = g_rowstart[gw];
    int e = g_rowstart[gw + 1];

    float a0 = 0.f, a1 = 0.f, a2 = 0.f, a3 = 0.f;
    const __half* __restrict__ h = g_h16;
    for (int p = s; p < e; p++) {
        uint2 pk = __ldg(&g_edge[p]);
        int   c = (int)pk.x;
        float v = __uint_as_float(pk.y);
        uint2 hv = *(const uint2*)(h + (size_t)c * D + lane * 4);
        float2 f0 = __half22float2(*(__half2*)&hv.x);
        float2 f1 = __half22float2(*(__half2*)&hv.y);
        a0 += v * f0.x;
        a1 += v * f0.y;
        a2 += v * f1.x;
        a3 += v * f1.y;
    }
    float4 o;
    o.x = fmaxf(a0, 0.f);
    o.y = fmaxf(a1, 0.f);
    o.z = fmaxf(a2, 0.f);
    o.w = fmaxf(a3, 0.f);
    // streaming store: out is write-once/never-read; keep it out of L2 so h stays resident
    __stcs((float4*)(out + (size_t)gw * D + lane * 4), o);
}

// ---------------- launch ----------------
extern "C" void kernel_launch(void* const* d_in, const int* in_sizes, int n_in,
                              void* d_out, int out_size)
{
    const float* x  = (const float*)d_in[0];
    const float* w  = (const float*)d_in[1];
    const float* ev = (const float*)d_in[2];
    const int*   er = (const int*)d_in[3];
    const int*   ec = (const int*)d_in[4];
    float* out = (float*)d_out;

    const int n = in_sizes[0] / D;      // 100000
    const int e = in_sizes[2];          // 1600000

    cudaFuncSetAttribute(gemm_tc_kernel, cudaFuncAttributeMaxDynamicSharedMemorySize, SM_TOT);

    const bool fork = (g_s1 != nullptr) && (g_ev_fork != nullptr) && (g_ev_join != nullptr);

    if (fork) {
        // fork at the very top: GEMM branch (wsplit + gemm) fully off the critical path
        cudaEventRecord(g_ev_fork, 0);
        cudaStreamWaitEvent(g_s1, g_ev_fork, 0);
        wsplit_kernel<<<64, 256, 0, g_s1>>>(w);
        gemm_tc_kernel<<<(n + 127) / 128, 256, SM_TOT, g_s1>>>(x, n);
        cudaEventRecord(g_ev_join, g_s1);

        // critical path starts immediately at hist (cnt/flags pre-zeroed by prior agg)
        hist_kernel<<<(e + 1023) / 1024, 256>>>(er, e);
        scan_kernel<<<(n + 4095) / 4096, 1024>>>(n);
        fill_kernel<<<(e + 1023) / 1024, 256>>>(er, ec, ev, e);

        cudaStreamWaitEvent(0, g_ev_join, 0);
    } else {
        wsplit_kernel<<<64, 256>>>(w);
        hist_kernel<<<(e + 1023) / 1024, 256>>>(er, e);
        scan_kernel<<<(n + 4095) / 4096, 1024>>>(n);
        fill_kernel<<<(e + 1023) / 1024, 256>>>(er, ec, ev, e);
        gemm_tc_kernel<<<(n + 127) / 128, 256, SM_TOT>>>(x, n);
    }

    int total_threads = n * 32;
    agg_kernel<<<(total_threads + 255) / 256, 256>>>(out, n);
}

// round 17
// speedup vs baseline: 1.0387x; 1.0387x over previous
#include <cuda_runtime.h>
#include <cuda_bf16.h>
#include <cuda_fp16.h>
#include <cstdint>

#define D 128
#define MAX_N 100000
#define MAX_E 1600000

// ---------------- scratch (static device globals; no allocation) ----------------
__device__ __align__(16) __half g_h16[(size_t)MAX_N * D];   // x @ W, fp16
__device__ __align__(16) int   g_cnt[MAX_N + 4];
__device__ int   g_rowstart[MAX_N + 1];
__device__ __align__(16) unsigned short g_slot16[MAX_E];    // per-edge slot within its row (u16)
__device__ __align__(16) uint2 g_edge[MAX_E];               // packed {col, val}
__device__ __align__(16) __nv_bfloat16 g_wt_hi[D * D];      // W^T split, [n][k]
__device__ __align__(16) __nv_bfloat16 g_wt_lo[D * D];
__device__ int   g_blk_aggr[128];
__device__ int   g_blk_flag[128];

// ---------------- side stream + events for graph-captured fork/join ----------------
static cudaStream_t g_s1 = nullptr;
static cudaEvent_t  g_ev_fork = nullptr, g_ev_join = nullptr;
namespace {
struct StreamInit {
    StreamInit() {
        if (cudaStreamCreateWithFlags(&g_s1, cudaStreamNonBlocking) != cudaSuccess) g_s1 = nullptr;
        if (cudaEventCreateWithFlags(&g_ev_fork, cudaEventDisableTiming) != cudaSuccess) g_ev_fork = nullptr;
        if (cudaEventCreateWithFlags(&g_ev_join, cudaEventDisableTiming) != cudaSuccess) g_ev_join = nullptr;
    }
};
static StreamInit s_init;
}

// =============== prep: W split + zero cnt + reset scan flags ===============
__global__ void prep_kernel(const float* __restrict__ w, int n)
{
    int i = blockIdx.x * blockDim.x + threadIdx.x;
    if (i < D * D) {
        int k = i >> 7, nn = i & 127;
        float v = w[i];                               // w[k*128+n]
        __nv_bfloat16 hi = __float2bfloat16_rn(v);
        float lo = v - __bfloat162float(hi);
        g_wt_hi[nn * D + k] = hi;
        g_wt_lo[nn * D + k] = __float2bfloat16_rn(lo);
    }
    if (i <= n) g_cnt[i] = 0;
    if (i < 128) { g_blk_flag[i] = 0; g_blk_aggr[i] = 0; }
}

// ---------------- CSR build ----------------
// hist also assigns each edge its slot within its row (atomic return value, u16)
__global__ void hist_kernel(const int* __restrict__ rows, int e)
{
    int i0 = (blockIdx.x * blockDim.x + threadIdx.x) * 4;
    if (i0 + 3 < e) {
        int4 r = *(const int4*)(rows + i0);
        ushort4 s;
        s.x = (unsigned short)atomicAdd(&g_cnt[r.x], 1);
        s.y = (unsigned short)atomicAdd(&g_cnt[r.y], 1);
        s.z = (unsigned short)atomicAdd(&g_cnt[r.z], 1);
        s.w = (unsigned short)atomicAdd(&g_cnt[r.w], 1);
        *(ushort4*)(g_slot16 + i0) = s;               // coalesced 8B store
    } else {
        for (int i = i0; i < e; i++)
            g_slot16[i] = (unsigned short)atomicAdd(&g_cnt[rows[i]], 1);
    }
}

// single-pass scan, 4 elems/thread, shuffle-based; decoupled lookback (25 blocks, 1 wave)
__global__ void scan_kernel(int n)
{
    __shared__ int warpsum[32];
    __shared__ int pref;
    const int b = blockIdx.x;
    const int tid = threadIdx.x;
    const int lane = tid & 31, wid = tid >> 5;
    const int base = b * 4096 + tid * 4;

    int4 v = make_int4(0, 0, 0, 0);
    if (base + 3 < n) {
        v = *(const int4*)(g_cnt + base);
    } else {
        if (base + 0 < n) v.x = g_cnt[base + 0];
        if (base + 1 < n) v.y = g_cnt[base + 1];
        if (base + 2 < n) v.z = g_cnt[base + 2];
        if (base + 3 < n) v.w = g_cnt[base + 3];
    }
    int s1 = v.x + v.y, s2 = s1 + v.z, s3 = s2 + v.w;
    int tsum = s3;

    int sc = tsum;
    #pragma unroll
    for (int o = 1; o < 32; o <<= 1) {
        int t = __shfl_up_sync(0xFFFFFFFFu, sc, o);
        if (lane >= o) sc += t;
    }
    if (lane == 31) warpsum[wid] = sc;
    if (tid == 0) pref = 0;
    __syncthreads();
    if (wid == 0) {
        int ws = warpsum[lane];
        #pragma unroll
        for (int o = 1; o < 32; o <<= 1) {
            int t = __shfl_up_sync(0xFFFFFFFFu, ws, o);
            if (lane >= o) ws += t;
        }
        warpsum[lane] = ws;
    }
    __syncthreads();

    if (tid == 0) {
        g_blk_aggr[b] = warpsum[31];
        __threadfence();
        atomicExch(&g_blk_flag[b], 1);
    }
    if (tid < b) {
        while (atomicAdd(&g_blk_flag[tid], 0) == 0) { }
        atomicAdd(&pref, g_blk_aggr[tid]);
    }
    __syncthreads();

    const int wpref = (wid > 0) ? warpsum[wid - 1] : 0;
    const int off = pref + wpref + (sc - tsum);

    if (base + 0 < n) g_rowstart[base + 1] = off + v.x;
    if (base + 1 < n) g_rowstart[base + 2] = off + s1;
    if (base + 2 < n) g_rowstart[base + 3] = off + s2;
    if (base + 3 < n) g_rowstart[base + 4] = off + s3;
    if (b == 0 && tid == 0) g_rowstart[0] = 0;
}

// atomic-free fill: position = rowstart[row] + precomputed slot
__global__ void fill_kernel(const int* __restrict__ rows, const int* __restrict__ cols,
                            const float* __restrict__ vals, int e)
{
    int i0 = (blockIdx.x * blockDim.x + threadIdx.x) * 4;
    if (i0 + 3 < e) {
        int4    r = *(const int4*)(rows + i0);
        int4    c = *(const int4*)(cols + i0);
        float4  v = *(const float4*)(vals + i0);
        ushort4 s = *(const ushort4*)(g_slot16 + i0);
        int p0 = g_rowstart[r.x] + s.x;
        int p1 = g_rowstart[r.y] + s.y;
        int p2 = g_rowstart[r.z] + s.z;
        int p3 = g_rowstart[r.w] + s.w;
        g_edge[p0] = make_uint2((unsigned)c.x, __float_as_uint(v.x));
        g_edge[p1] = make_uint2((unsigned)c.y, __float_as_uint(v.y));
        g_edge[p2] = make_uint2((unsigned)c.z, __float_as_uint(v.z));
        g_edge[p3] = make_uint2((unsigned)c.w, __float_as_uint(v.w));
    } else {
        for (int i = i0; i < e; i++) {
            int p = g_rowstart[rows[i]] + (int)g_slot16[i];
            g_edge[p] = make_uint2((unsigned)cols[i], __float_as_uint(vals[i]));
        }
    }
}

// =============== GEMM: h = x @ W via mma.sync bf16, 3-product split ===============
#define AS 136
#define SM_AHI 0
#define SM_ALO (128 * AS * 2)
#define SM_BHI (2 * 128 * AS * 2)
#define SM_BLO (3 * 128 * AS * 2)
#define SM_TOT (4 * 128 * AS * 2)

__device__ __forceinline__ void mma_bf16(float* c, const uint32_t* a, uint32_t b0, uint32_t b1)
{
    asm volatile(
        "mma.sync.aligned.m16n8k16.row.col.f32.bf16.bf16.f32 "
        "{%0,%1,%2,%3}, {%4,%5,%6,%7}, {%8,%9}, {%0,%1,%2,%3};"
        : "+f"(c[0]), "+f"(c[1]), "+f"(c[2]), "+f"(c[3])
        : "r"(a[0]), "r"(a[1]), "r"(a[2]), "r"(a[3]), "r"(b0), "r"(b1));
}

__global__ void __launch_bounds__(256, 1)
gemm_tc_kernel(const float* __restrict__ x, int n)
{
    extern __shared__ char smem[];
    __nv_bfloat16* sAhi = (__nv_bfloat16*)(smem + SM_AHI);
    __nv_bfloat16* sAlo = (__nv_bfloat16*)(smem + SM_ALO);
    __nv_bfloat16* sBhi = (__nv_bfloat16*)(smem + SM_BHI);
    __nv_bfloat16* sBlo = (__nv_bfloat16*)(smem + SM_BLO);

    const int tid = threadIdx.x;
    const int m0  = blockIdx.x * 128;

    #pragma unroll
    for (int t = 0; t < 8; t++) {
        int i = tid + 256 * t;
        int row = i >> 4, kc = (i & 15) * 8;
        uint4 vh = *(const uint4*)(g_wt_hi + row * D + kc);
        uint4 vl = *(const uint4*)(g_wt_lo + row * D + kc);
        *(uint4*)(sBhi + row * AS + kc) = vh;
        *(uint4*)(sBlo + row * AS + kc) = vl;
    }
    #pragma unroll
    for (int t = 0; t < 16; t++) {
        int i = tid + 256 * t;
        int row = i >> 5, c4 = (i & 31) * 4;
        int gm = m0 + row;
        float4 v = (gm < n) ? *(const float4*)(x + (size_t)gm * D + c4)
                            : make_float4(0.f, 0.f, 0.f, 0.f);
        __nv_bfloat16 h0 = __float2bfloat16_rn(v.x), h1 = __float2bfloat16_rn(v.y);
        __nv_bfloat16 h2 = __float2bfloat16_rn(v.z), h3 = __float2bfloat16_rn(v.w);
        __nv_bfloat16 l0 = __float2bfloat16_rn(v.x - __bfloat162float(h0));
        __nv_bfloat16 l1 = __float2bfloat16_rn(v.y - __bfloat162float(h1));
        __nv_bfloat16 l2 = __float2bfloat16_rn(v.z - __bfloat162float(h2));
        __nv_bfloat16 l3 = __float2bfloat16_rn(v.w - __bfloat162float(h3));
        uint32_t hp0 = ((uint32_t)__bfloat16_as_ushort(h1) << 16) | __bfloat16_as_ushort(h0);
        uint32_t hp1 = ((uint32_t)__bfloat16_as_ushort(h3) << 16) | __bfloat16_as_ushort(h2);
        uint32_t lp0 = ((uint32_t)__bfloat16_as_ushort(l1) << 16) | __bfloat16_as_ushort(l0);
        uint32_t lp1 = ((uint32_t)__bfloat16_as_ushort(l3) << 16) | __bfloat16_as_ushort(l2);
        uint2 hq; hq.x = hp0; hq.y = hp1;
        uint2 lq; lq.x = lp0; lq.y = lp1;
        *(uint2*)(sAhi + row * AS + c4) = hq;
        *(uint2*)(sAlo + row * AS + c4) = lq;
    }
    __syncthreads();

    const int wid  = tid >> 5;
    const int lane = tid & 31;
    const int g = lane >> 2, q = lane & 3;
    const int m_base = (wid & 3) * 32;
    const int n_base = (wid >> 2) * 64;

    float acc[2][8][4];
    #pragma unroll
    for (int mi = 0; mi < 2; mi++)
        #pragma unroll
        for (int ni = 0; ni < 8; ni++)
            #pragma unroll
            for (int r = 0; r < 4; r++) acc[mi][ni][r] = 0.f;

    #pragma unroll
    for (int prod = 0; prod < 3; prod++) {
        const __nv_bfloat16* A = (prod == 2) ? sAlo : sAhi;
        const __nv_bfloat16* B = (prod == 1) ? sBlo : sBhi;
        #pragma unroll
        for (int ks = 0; ks < 8; ks++) {
            const int k0 = ks * 16;
            uint32_t a[2][4];
            #pragma unroll
            for (int mi = 0; mi < 2; mi++) {
                const int r0 = m_base + mi * 16;
                a[mi][0] = *(const uint32_t*)(A + (r0 + g)     * AS + k0     + q * 2);
                a[mi][1] = *(const uint32_t*)(A + (r0 + g + 8) * AS + k0     + q * 2);
                a[mi][2] = *(const uint32_t*)(A + (r0 + g)     * AS + k0 + 8 + q * 2);
                a[mi][3] = *(const uint32_t*)(A + (r0 + g + 8) * AS + k0 + 8 + q * 2);
            }
            #pragma unroll
            for (int ni = 0; ni < 8; ni++) {
                const int nr = n_base + ni * 8 + g;
                uint32_t b0 = *(const uint32_t*)(B + nr * AS + k0     + q * 2);
                uint32_t b1 = *(const uint32_t*)(B + nr * AS + k0 + 8 + q * 2);
                mma_bf16(acc[0][ni], a[0], b0, b1);
                mma_bf16(acc[1][ni], a[1], b0, b1);
            }
        }
    }

    #pragma unroll
    for (int mi = 0; mi < 2; mi++) {
        const int r0 = m0 + m_base + mi * 16;
        #pragma unroll
        for (int ni = 0; ni < 8; ni++) {
            const int col = n_base + ni * 8 + q * 2;
            int ra = r0 + g, rb = r0 + g + 8;
            if (ra < n)
                *(__half2*)(g_h16 + (size_t)ra * D + col) =
                    __floats2half2_rn(acc[mi][ni][0], acc[mi][ni][1]);
            if (rb < n)
                *(__half2*)(g_h16 + (size_t)rb * D + col) =
                    __floats2half2_rn(acc[mi][ni][2], acc[mi][ni][3]);
        }
    }
}

// ---------------- aggregation: one warp per row (champion form) + streaming out store ----------------
__global__ void agg_kernel(float* __restrict__ out, int n)
{
    int gw   = (blockIdx.x * blockDim.x + threadIdx.x) >> 5;
    int lane = threadIdx.x & 31;
    if (gw >= n) return;

    int s = g_rowstart[gw];
    int e = g_rowstart[gw + 1];

    float a0 = 0.f, a1 = 0.f, a2 = 0.f, a3 = 0.f;
    const __half* __restrict__ h = g_h16;
    for (int p = s; p < e; p++) {
        uint2 pk = __ldg(&g_edge[p]);
        int   c = (int)pk.x;
        float v = __uint_as_float(pk.y);
        uint2 hv = *(const uint2*)(h + (size_t)c * D + lane * 4);
        float2 f0 = __half22float2(*(__half2*)&hv.x);
        float2 f1 = __half22float2(*(__half2*)&hv.y);
        a0 += v * f0.x;
        a1 += v * f0.y;
        a2 += v * f1.x;
        a3 += v * f1.y;
    }
    float4 o;
    o.x = fmaxf(a0, 0.f);
    o.y = fmaxf(a1, 0.f);
    o.z = fmaxf(a2, 0.f);
    o.w = fmaxf(a3, 0.f);
    // streaming store: out is write-once/never-read; keep it out of L2 so h stays resident
    __stcs((float4*)(out + (size_t)gw * D + lane * 4), o);
}

// ---------------- launch ----------------
extern "C" void kernel_launch(void* const* d_in, const int* in_sizes, int n_in,
                              void* d_out, int out_size)
{
    const float* x  = (const float*)d_in[0];
    const float* w  = (const float*)d_in[1];
    const float* ev = (const float*)d_in[2];
    const int*   er = (const int*)d_in[3];
    const int*   ec = (const int*)d_in[4];
    float* out = (float*)d_out;

    const int n = in_sizes[0] / D;      // 100000
    const int e = in_sizes[2];          // 1600000

    cudaFuncSetAttribute(gemm_tc_kernel, cudaFuncAttributeMaxDynamicSharedMemorySize, SM_TOT);

    const bool fork = (g_s1 != nullptr) && (g_ev_fork != nullptr) && (g_ev_join != nullptr);

    prep_kernel<<<(n + 256) / 256, 256>>>(w, n);

    if (fork) {
        cudaEventRecord(g_ev_fork, 0);
        cudaStreamWaitEvent(g_s1, g_ev_fork, 0);
        gemm_tc_kernel<<<(n + 127) / 128, 256, SM_TOT, g_s1>>>(x, n);
        cudaEventRecord(g_ev_join, g_s1);

        hist_kernel<<<(e + 1023) / 1024, 256>>>(er, e);
        scan_kernel<<<(n + 4095) / 4096, 1024>>>(n);
        fill_kernel<<<(e + 1023) / 1024, 256>>>(er, ec, ev, e);

        cudaStreamWaitEvent(0, g_ev_join, 0);
    } else {
        hist_kernel<<<(e + 1023) / 1024, 256>>>(er, e);
        scan_kernel<<<(n + 4095) / 4096, 1024>>>(n);
        fill_kernel<<<(e + 1023) / 1024, 256>>>(er, ec, ev, e);
        gemm_tc_kernel<<<(n + 127) / 128, 256, SM_TOT>>>(x, n);
    }

    int total_threads = n * 32;
    agg_kernel<<<(total_threads + 255) / 256, 256>>>(out, n);
}